// round 6
// baseline (speedup 1.0000x reference)
#include <cuda_runtime.h>
#include <cuda_bf16.h>
#include <math.h>

// Problem constants
static constexpr int   N_NODES  = 200000;
static constexpr int   N_USERS  = 100000;
static constexpr int   DIM      = 64;
static constexpr int   LAYERS   = 3;
static constexpr long  E_EDGES  = 3000000;
static constexpr int   N_LINK   = 100000;
static constexpr int   EMB_COLS = (LAYERS + 1) * DIM;          // 256
static constexpr int   NB_SCAN  = (N_NODES + 1023) / 1024;     // 196

// ---------------------------------------------------------------------------
// Scratch (static device globals; no allocation allowed in kernel_launch)
// ---------------------------------------------------------------------------
__device__ int   g_deg_s[N_NODES],  g_deg_t[N_NODES];
__device__ int   g_row_s[N_NODES],  g_row_t[N_NODES];     // exclusive prefix (CSR rowptr)
__device__ int   g_cur_s[N_NODES],  g_cur_t[N_NODES];     // fill cursors
__device__ int   g_csr_s[E_EDGES],  g_csr_t[E_EDGES];     // neighbor (src) lists per dst
__device__ int   g_ps_s[256],       g_ps_t[256];          // scan partials
__device__ float g_invdeg_s[N_NODES], g_invdeg_t[N_NODES];
__device__ float g_means[(size_t)N_NODES * DIM];          // source-graph means
__device__ float g_meant[(size_t)N_NODES * DIM];          // target-graph means
__device__ float g_xt   [(size_t)N_NODES * DIM];          // target_x for next layer
__device__ float g_embs [(size_t)N_NODES * EMB_COLS];     // [N,256]: [emb|x1|x2|x3]

// ---------------------------------------------------------------------------
// CSR build: zero -> histogram -> 2-level exclusive scan -> cursor fill
// ---------------------------------------------------------------------------
__global__ void k_zero_deg() {
    int i = blockIdx.x * blockDim.x + threadIdx.x;
    if (i < N_NODES) { g_deg_s[i] = 0; g_deg_t[i] = 0; }
}

__global__ void k_hist(const int* __restrict__ s_dst, const int* __restrict__ t_dst) {
    long e = (long)blockIdx.x * blockDim.x + threadIdx.x;
    if (e < E_EDGES) {
        atomicAdd(&g_deg_s[s_dst[e]], 1);
        atomicAdd(&g_deg_t[t_dst[e]], 1);
    }
}

// Per-1024-chunk exclusive scan; blockIdx.y selects graph (0=source, 1=target)
__global__ void k_scan1() {
    __shared__ int sh[1024];
    const int* deg = blockIdx.y ? g_deg_t : g_deg_s;
    int*       row = blockIdx.y ? g_row_t : g_row_s;
    int*       ps  = blockIdx.y ? g_ps_t  : g_ps_s;

    int i = blockIdx.x * 1024 + threadIdx.x;
    int v = (i < N_NODES) ? deg[i] : 0;
    sh[threadIdx.x] = v;
    __syncthreads();
    #pragma unroll
    for (int off = 1; off < 1024; off <<= 1) {
        int t = (threadIdx.x >= off) ? sh[threadIdx.x - off] : 0;
        __syncthreads();
        sh[threadIdx.x] += t;
        __syncthreads();
    }
    if (i < N_NODES) row[i] = sh[threadIdx.x] - v;        // exclusive
    if (threadIdx.x == 1023) ps[blockIdx.x] = sh[1023];
}

// Scan the (<=256) block partials for both graphs
__global__ void k_scan2() {
    __shared__ int sh[256];
    int t = threadIdx.x;

    int v = (t < NB_SCAN) ? g_ps_s[t] : 0;
    sh[t] = v; __syncthreads();
    #pragma unroll
    for (int off = 1; off < 256; off <<= 1) {
        int u = (t >= off) ? sh[t - off] : 0;
        __syncthreads(); sh[t] += u; __syncthreads();
    }
    if (t < NB_SCAN) g_ps_s[t] = sh[t] - v;
    __syncthreads();

    v = (t < NB_SCAN) ? g_ps_t[t] : 0;
    sh[t] = v; __syncthreads();
    #pragma unroll
    for (int off = 1; off < 256; off <<= 1) {
        int u = (t >= off) ? sh[t - off] : 0;
        __syncthreads(); sh[t] += u; __syncthreads();
    }
    if (t < NB_SCAN) g_ps_t[t] = sh[t] - v;
}

// Apply block offsets; init cursors; compute reciprocal degrees
__global__ void k_scan3() {
    int i = blockIdx.x * blockDim.x + threadIdx.x;
    if (i >= N_NODES) return;
    int b = i >> 10;
    int rs = g_row_s[i] + g_ps_s[b];
    int rt = g_row_t[i] + g_ps_t[b];
    g_row_s[i] = rs;  g_cur_s[i] = rs;
    g_row_t[i] = rt;  g_cur_t[i] = rt;
    g_invdeg_s[i] = 1.f / fmaxf((float)g_deg_s[i], 1.f);
    g_invdeg_t[i] = 1.f / fmaxf((float)g_deg_t[i], 1.f);
}

__global__ void k_fill(const int* __restrict__ s_src, const int* __restrict__ s_dst,
                       const int* __restrict__ t_src, const int* __restrict__ t_dst) {
    long e = (long)blockIdx.x * blockDim.x + threadIdx.x;
    if (e < E_EDGES) {
        int ps = atomicAdd(&g_cur_s[s_dst[e]], 1);
        g_csr_s[ps] = s_src[e];
        int pt = atomicAdd(&g_cur_t[t_dst[e]], 1);
        g_csr_t[pt] = t_src[e];
    }
}

// ---------------------------------------------------------------------------
// Copy emb (vectorized) into column block 0 of the [N,256] embedding table
// ---------------------------------------------------------------------------
__global__ void k_copy_emb(const float4* __restrict__ emb4) {
    long i = (long)blockIdx.x * blockDim.x + threadIdx.x;     // N*16 float4s
    if (i < (long)N_NODES * (DIM / 4)) {
        long v = i >> 4;           // / 16
        int  d = (int)(i & 15);
        reinterpret_cast<float4*>(g_embs)[v * (EMB_COLS / 4) + d] = emb4[i];
    }
}

// ---------------------------------------------------------------------------
// Fused gather conv (both graphs): warp per (graph,node). 16 lanes per row
// with float4 loads => 2 neighbors per iteration, halving LDG instruction
// count vs float2 (the binding resource is LSU issue, not bytes).
// ---------------------------------------------------------------------------
__global__ void __launch_bounds__(256)
k_conv2(const float* __restrict__ xs, int xs_stride,
        const float* __restrict__ xt) {
    int gw = (blockIdx.x * blockDim.x + threadIdx.x) >> 5;
    if (gw >= 2 * N_NODES) return;
    int  lane = threadIdx.x & 31;
    bool tgt  = gw >= N_NODES;
    int  v    = tgt ? gw - N_NODES : gw;

    const int*   rowptr = tgt ? g_row_t    : g_row_s;
    const int*   degp   = tgt ? g_deg_t    : g_deg_s;
    const float* invd   = tgt ? g_invdeg_t : g_invdeg_s;
    const int*   csr    = tgt ? g_csr_t    : g_csr_s;
    const float* x      = tgt ? xt         : xs;
    const int    xstr   = tgt ? DIM        : xs_stride;
    float*       om     = tgt ? g_meant    : g_means;

    int start = rowptr[v];
    int d     = degp[v];
    int h     = lane >> 4;     // which of 2 edges this half-warp handles
    int c     = lane & 15;     // float4 chunk within the 64-float row

    float4 acc = make_float4(0.f, 0.f, 0.f, 0.f);

    for (int j0 = 0; j0 < d; j0 += 32) {
        int idx = (j0 + lane < d) ? __ldg(&csr[start + j0 + lane]) : 0;
        int m   = min(32, d - j0);
        if (m == 32) {
            #pragma unroll
            for (int j = 0; j < 32; j += 2) {
                int s = __shfl_sync(0xffffffffu, idx, j + h);
                float4 vv = __ldg(reinterpret_cast<const float4*>(
                                      x + (size_t)s * xstr) + c);
                acc.x += vv.x; acc.y += vv.y; acc.z += vv.z; acc.w += vv.w;
            }
        } else {
            for (int j = 0; j < m; j += 2) {
                int jj = j + h;
                int s  = __shfl_sync(0xffffffffu, idx, jj);
                if (jj < m) {
                    float4 vv = __ldg(reinterpret_cast<const float4*>(
                                          x + (size_t)s * xstr) + c);
                    acc.x += vv.x; acc.y += vv.y; acc.z += vv.z; acc.w += vv.w;
                }
            }
        }
    }

    // fold the two half-warp edge streams together
    acc.x += __shfl_down_sync(0xffffffffu, acc.x, 16);
    acc.y += __shfl_down_sync(0xffffffffu, acc.y, 16);
    acc.z += __shfl_down_sync(0xffffffffu, acc.z, 16);
    acc.w += __shfl_down_sync(0xffffffffu, acc.w, 16);

    if (h == 0) {
        float iv = invd[v];
        float4 o = make_float4(acc.x * iv, acc.y * iv, acc.z * iv, acc.w * iv);
        reinterpret_cast<float4*>(om + (size_t)v * DIM)[c] = o;
    }
}

// ---------------------------------------------------------------------------
// Combine: users get mix GEMM ue=[ms|mt]@W^T+b; write source slice into
// g_embs(layer+1) and target into g_xt. One warp per node; WT in smem.
// ---------------------------------------------------------------------------
__global__ void __launch_bounds__(256)
k_combine(const float* __restrict__ mix_w, const float* __restrict__ mix_b, int layer) {
    __shared__ float WT[128 * 64];   // WT[k*64 + d] = W[d,k]   (32 KB)
    __shared__ float BB[64];

    const float* W = mix_w + (size_t)layer * 64 * 128;
    for (int i = threadIdx.x; i < 64 * 128; i += blockDim.x) {
        int k = i >> 6, d = i & 63;
        WT[i] = W[d * 128 + k];
    }
    if (threadIdx.x < 64) BB[threadIdx.x] = mix_b[layer * 64 + threadIdx.x];
    __syncthreads();

    int lane = threadIdx.x & 31;
    int warp = threadIdx.x >> 5;
    int wpb  = blockDim.x >> 5;

    for (int v = blockIdx.x * wpb + warp; v < N_NODES; v += gridDim.x * wpb) {
        size_t base = (size_t)v * DIM;

        float ms0 = g_means[base + lane];
        float ms1 = g_means[base + 32 + lane];
        float mt0 = g_meant[base + lane];
        float mt1 = g_meant[base + 32 + lane];

        float o0, o1, t0, t1;
        if (v < N_USERS) {
            float a0 = BB[lane], a1 = BB[lane + 32];
            #pragma unroll
            for (int k = 0; k < 32; k++) {
                float m = __shfl_sync(0xffffffffu, ms0, k);
                a0 += m * WT[k * 64 + lane];
                a1 += m * WT[k * 64 + lane + 32];
            }
            #pragma unroll
            for (int k = 0; k < 32; k++) {
                float m = __shfl_sync(0xffffffffu, ms1, k);
                a0 += m * WT[(k + 32) * 64 + lane];
                a1 += m * WT[(k + 32) * 64 + lane + 32];
            }
            #pragma unroll
            for (int k = 0; k < 32; k++) {
                float m = __shfl_sync(0xffffffffu, mt0, k);
                a0 += m * WT[(k + 64) * 64 + lane];
                a1 += m * WT[(k + 64) * 64 + lane + 32];
            }
            #pragma unroll
            for (int k = 0; k < 32; k++) {
                float m = __shfl_sync(0xffffffffu, mt1, k);
                a0 += m * WT[(k + 96) * 64 + lane];
                a1 += m * WT[(k + 96) * 64 + lane + 32];
            }
            o0 = a0; o1 = a1; t0 = a0; t1 = a1;   // users: both paths get user_emb
        } else {
            o0 = ms0; o1 = ms1; t0 = mt0; t1 = mt1;
        }

        g_xt[base + lane]      = t0;
        g_xt[base + 32 + lane] = t1;
        float* er = g_embs + (size_t)v * EMB_COLS + (size_t)(layer + 1) * DIM;
        er[lane]      = o0;
        er[lane + 32] = o1;
    }
}

// ---------------------------------------------------------------------------
// Prediction head: warp per link. dot([ue|ie], pred_w)+b -> leaky_relu -> sigmoid
// ---------------------------------------------------------------------------
__global__ void k_pred(const int* __restrict__ link,
                       const float* __restrict__ pred_w,
                       const float* __restrict__ pred_b,
                       float* __restrict__ out) {
    __shared__ float pw[512];
    for (int i = threadIdx.x; i < 512; i += blockDim.x) pw[i] = pred_w[i];
    __syncthreads();

    int lane = threadIdx.x & 31;
    int warp = threadIdx.x >> 5;
    int j = blockIdx.x * (blockDim.x >> 5) + warp;
    if (j >= N_LINK) return;

    int u  = __ldg(&link[j]);
    int it = __ldg(&link[N_LINK + j]);
    const float* ue = g_embs + (size_t)u  * EMB_COLS;
    const float* ie = g_embs + (size_t)it * EMB_COLS;

    float acc = 0.f;
    #pragma unroll
    for (int c = 0; c < 8; c++) acc += ue[lane + c * 32] * pw[lane + c * 32];
    #pragma unroll
    for (int c = 0; c < 8; c++) acc += ie[lane + c * 32] * pw[256 + lane + c * 32];

    #pragma unroll
    for (int o = 16; o > 0; o >>= 1) acc += __shfl_down_sync(0xffffffffu, acc, o);

    if (lane == 0) {
        float z = acc + pred_b[0];
        z = (z >= 0.f) ? z : 0.01f * z;          // leaky_relu(0.01)
        out[j] = 1.f / (1.f + expf(-z));         // sigmoid
    }
}

// ---------------------------------------------------------------------------
// Launch
// ---------------------------------------------------------------------------
extern "C" void kernel_launch(void* const* d_in, const int* in_sizes, int n_in,
                              void* d_out, int out_size) {
    const int*   sei    = (const int*)  d_in[0];   // [2,E] source graph
    const int*   tei    = (const int*)  d_in[1];   // [2,E] target graph
    const int*   link   = (const int*)  d_in[2];   // [2,NLINK]
    const float* emb    = (const float*)d_in[3];   // [N,64]
    const float* mix_w  = (const float*)d_in[4];   // [3,64,128]
    const float* mix_b  = (const float*)d_in[5];   // [3,64]
    const float* pred_w = (const float*)d_in[6];   // [1,512]
    const float* pred_b = (const float*)d_in[7];   // [1]
    float*       out    = (float*)d_out;           // [NLINK]

    const int* s_src = sei;
    const int* s_dst = sei + E_EDGES;
    const int* t_src = tei;
    const int* t_dst = tei + E_EDGES;

    // ---- CSR build (edge lists are layer-invariant) ----
    k_zero_deg<<<(N_NODES + 255) / 256, 256>>>();
    k_hist<<<(int)((E_EDGES + 255) / 256), 256>>>(s_dst, t_dst);
    k_scan1<<<dim3(NB_SCAN, 2), 1024>>>();
    k_scan2<<<1, 256>>>();
    k_scan3<<<(N_NODES + 255) / 256, 256>>>();
    k_fill<<<(int)((E_EDGES + 255) / 256), 256>>>(s_src, s_dst, t_src, t_dst);

    k_copy_emb<<<(int)(((long)N_NODES * 16 + 255) / 256), 256>>>(
        reinterpret_cast<const float4*>(emb));

    const int conv_blocks = (int)((2L * N_NODES * 32 + 255) / 256);  // 2N warps

    for (int l = 0; l < LAYERS; l++) {
        const float* xs = (l == 0) ? emb : (g_embs + (size_t)l * DIM);
        int xs_stride   = (l == 0) ? DIM : EMB_COLS;
        const float* xtp = (l == 0) ? emb : g_xt;
        k_conv2<<<conv_blocks, 256>>>(xs, xs_stride, xtp);
        k_combine<<<2960, 256>>>(mix_w, mix_b, l);
    }

    k_pred<<<(N_LINK + 7) / 8, 256>>>(link, pred_w, pred_b, out);
}

// round 7
// speedup vs baseline: 6.9768x; 6.9768x over previous
#include <cuda_runtime.h>
#include <cuda_bf16.h>
#include <math.h>

// Problem constants
static constexpr int   N_NODES  = 200000;
static constexpr int   N_USERS  = 100000;
static constexpr int   DIM      = 64;
static constexpr int   LAYERS   = 3;
static constexpr long  E_EDGES  = 3000000;
static constexpr int   N_LINK   = 100000;
static constexpr int   EMB_COLS = (LAYERS + 1) * DIM;          // 256
static constexpr int   NB_SCAN  = (N_NODES + 1023) / 1024;     // 196

// ---------------------------------------------------------------------------
// Scratch (static device globals; no allocation allowed in kernel_launch)
// ---------------------------------------------------------------------------
__device__ int   g_deg_s[N_NODES],  g_deg_t[N_NODES];
__device__ int   g_row_s[N_NODES],  g_row_t[N_NODES];     // exclusive prefix (CSR rowptr)
__device__ int   g_cur_s[N_NODES],  g_cur_t[N_NODES];     // fill cursors
__device__ int   g_csr_s[E_EDGES],  g_csr_t[E_EDGES];     // neighbor (src) lists per dst
__device__ int   g_ps_s[256],       g_ps_t[256];          // scan partials
__device__ float g_invdeg_s[N_NODES], g_invdeg_t[N_NODES];
__device__ float g_means[(size_t)N_NODES * DIM];          // source-graph means
__device__ float g_meant[(size_t)N_NODES * DIM];          // target-graph means
__device__ float g_xt   [(size_t)N_NODES * DIM];          // target_x for next layer
__device__ float g_embs [(size_t)N_NODES * EMB_COLS];     // [N,256]: [emb|x1|x2|x3]

// ---------------------------------------------------------------------------
// CSR build: zero -> histogram -> 2-level exclusive scan -> cursor fill
// ---------------------------------------------------------------------------
__global__ void k_zero_deg() {
    int i = blockIdx.x * blockDim.x + threadIdx.x;
    if (i < N_NODES) { g_deg_s[i] = 0; g_deg_t[i] = 0; }
}

__global__ void k_hist(const int* __restrict__ s_dst, const int* __restrict__ t_dst) {
    long e = (long)blockIdx.x * blockDim.x + threadIdx.x;
    if (e < E_EDGES) {
        atomicAdd(&g_deg_s[s_dst[e]], 1);
        atomicAdd(&g_deg_t[t_dst[e]], 1);
    }
}

// Per-1024-chunk exclusive scan; blockIdx.y selects graph (0=source, 1=target)
__global__ void k_scan1() {
    __shared__ int sh[1024];
    const int* deg = blockIdx.y ? g_deg_t : g_deg_s;
    int*       row = blockIdx.y ? g_row_t : g_row_s;
    int*       ps  = blockIdx.y ? g_ps_t  : g_ps_s;

    int i = blockIdx.x * 1024 + threadIdx.x;
    int v = (i < N_NODES) ? deg[i] : 0;
    sh[threadIdx.x] = v;
    __syncthreads();
    #pragma unroll
    for (int off = 1; off < 1024; off <<= 1) {
        int t = (threadIdx.x >= off) ? sh[threadIdx.x - off] : 0;
        __syncthreads();
        sh[threadIdx.x] += t;
        __syncthreads();
    }
    if (i < N_NODES) row[i] = sh[threadIdx.x] - v;        // exclusive
    if (threadIdx.x == 1023) ps[blockIdx.x] = sh[1023];
}

// Scan the (<=256) block partials for both graphs
__global__ void k_scan2() {
    __shared__ int sh[256];
    int t = threadIdx.x;

    int v = (t < NB_SCAN) ? g_ps_s[t] : 0;
    sh[t] = v; __syncthreads();
    #pragma unroll
    for (int off = 1; off < 256; off <<= 1) {
        int u = (t >= off) ? sh[t - off] : 0;
        __syncthreads(); sh[t] += u; __syncthreads();
    }
    if (t < NB_SCAN) g_ps_s[t] = sh[t] - v;
    __syncthreads();

    v = (t < NB_SCAN) ? g_ps_t[t] : 0;
    sh[t] = v; __syncthreads();
    #pragma unroll
    for (int off = 1; off < 256; off <<= 1) {
        int u = (t >= off) ? sh[t - off] : 0;
        __syncthreads(); sh[t] += u; __syncthreads();
    }
    if (t < NB_SCAN) g_ps_t[t] = sh[t] - v;
}

// Apply block offsets; init cursors; compute reciprocal degrees
__global__ void k_scan3() {
    int i = blockIdx.x * blockDim.x + threadIdx.x;
    if (i >= N_NODES) return;
    int b = i >> 10;
    int rs = g_row_s[i] + g_ps_s[b];
    int rt = g_row_t[i] + g_ps_t[b];
    g_row_s[i] = rs;  g_cur_s[i] = rs;
    g_row_t[i] = rt;  g_cur_t[i] = rt;
    g_invdeg_s[i] = 1.f / fmaxf((float)g_deg_s[i], 1.f);
    g_invdeg_t[i] = 1.f / fmaxf((float)g_deg_t[i], 1.f);
}

__global__ void k_fill(const int* __restrict__ s_src, const int* __restrict__ s_dst,
                       const int* __restrict__ t_src, const int* __restrict__ t_dst) {
    long e = (long)blockIdx.x * blockDim.x + threadIdx.x;
    if (e < E_EDGES) {
        int ps = atomicAdd(&g_cur_s[s_dst[e]], 1);
        g_csr_s[ps] = s_src[e];
        int pt = atomicAdd(&g_cur_t[t_dst[e]], 1);
        g_csr_t[pt] = t_src[e];
    }
}

// ---------------------------------------------------------------------------
// Copy emb (vectorized) into column block 0 of the [N,256] embedding table
// ---------------------------------------------------------------------------
__global__ void k_copy_emb(const float4* __restrict__ emb4) {
    long i = (long)blockIdx.x * blockDim.x + threadIdx.x;     // N*16 float4s
    if (i < (long)N_NODES * (DIM / 4)) {
        long v = i >> 4;           // / 16
        int  d = (int)(i & 15);
        reinterpret_cast<float4*>(g_embs)[v * (EMB_COLS / 4) + d] = emb4[i];
    }
}

// ---------------------------------------------------------------------------
// Gather conv: HALF-WARP per destination node, float4 (LDG.128) per lane.
// 16 LDGs per edge (vs 32 with float2). Both code paths are branch-free in
// the load body so ptxas can batch the LDG stream (front-loaded MLP).
// Out-of-range neighbors are masked with a multiply (idx defaults to row 0).
// ---------------------------------------------------------------------------
__global__ void __launch_bounds__(256)
k_conv(const float* __restrict__ x, int xstr,
       const int* __restrict__ rowptr, const int* __restrict__ degp,
       const float* __restrict__ invd, const int* __restrict__ csr,
       float* __restrict__ om) {
    int w = (blockIdx.x * blockDim.x + threadIdx.x) >> 5;   // warp id
    if (w >= N_NODES / 2) return;
    int      lane = threadIdx.x & 31;
    int      h    = lane >> 4;                              // half-warp id
    int      c    = lane & 15;                              // float4 chunk in row
    unsigned hm   = h ? 0xFFFF0000u : 0x0000FFFFu;          // per-half shfl mask
    int      v    = 2 * w + h;                              // node for this half

    int start = rowptr[v];
    int d     = degp[v];

    float4 acc = make_float4(0.f, 0.f, 0.f, 0.f);

    for (int j0 = 0; j0 < d; j0 += 16) {
        int idx = (j0 + c < d) ? __ldg(&csr[start + j0 + c]) : 0;
        int kk  = min(16, d - j0);
        if (kk == 16) {
            // straight-line: 16 independent loads, fully batched
            #pragma unroll
            for (int j = 0; j < 16; j++) {
                int s = __shfl_sync(hm, idx, h * 16 + j);
                float4 vv = __ldg(reinterpret_cast<const float4*>(
                                      x + (size_t)s * xstr) + c);
                acc.x += vv.x; acc.y += vv.y; acc.z += vv.z; acc.w += vv.w;
            }
        } else {
            // remainder: 2 loads per iteration, tail masked by multiply (no if)
            for (int j = 0; j < kk; j += 2) {
                int s0 = __shfl_sync(hm, idx, h * 16 + j);
                int s1 = __shfl_sync(hm, idx, h * 16 + j + 1);
                float wt = (j + 1 < kk) ? 1.f : 0.f;
                float4 va = __ldg(reinterpret_cast<const float4*>(
                                      x + (size_t)s0 * xstr) + c);
                float4 vb = __ldg(reinterpret_cast<const float4*>(
                                      x + (size_t)s1 * xstr) + c);
                acc.x += va.x + vb.x * wt;
                acc.y += va.y + vb.y * wt;
                acc.z += va.z + vb.z * wt;
                acc.w += va.w + vb.w * wt;
            }
        }
    }

    float iv = invd[v];
    float4 o = make_float4(acc.x * iv, acc.y * iv, acc.z * iv, acc.w * iv);
    reinterpret_cast<float4*>(om + (size_t)v * DIM)[c] = o;
}

// ---------------------------------------------------------------------------
// Combine: users get mix GEMM ue=[ms|mt]@W^T+b; write source slice into
// g_embs(layer+1) and target into g_xt. One warp per node; WT in smem.
// ---------------------------------------------------------------------------
__global__ void __launch_bounds__(256)
k_combine(const float* __restrict__ mix_w, const float* __restrict__ mix_b, int layer) {
    __shared__ float WT[128 * 64];   // WT[k*64 + d] = W[d,k]   (32 KB)
    __shared__ float BB[64];

    const float* W = mix_w + (size_t)layer * 64 * 128;
    for (int i = threadIdx.x; i < 64 * 128; i += blockDim.x) {
        int k = i >> 6, d = i & 63;
        WT[i] = W[d * 128 + k];
    }
    if (threadIdx.x < 64) BB[threadIdx.x] = mix_b[layer * 64 + threadIdx.x];
    __syncthreads();

    int lane = threadIdx.x & 31;
    int warp = threadIdx.x >> 5;
    int wpb  = blockDim.x >> 5;

    for (int v = blockIdx.x * wpb + warp; v < N_NODES; v += gridDim.x * wpb) {
        size_t base = (size_t)v * DIM;

        float ms0 = g_means[base + lane];
        float ms1 = g_means[base + 32 + lane];
        float mt0 = g_meant[base + lane];
        float mt1 = g_meant[base + 32 + lane];

        float o0, o1, t0, t1;
        if (v < N_USERS) {
            float a0 = BB[lane], a1 = BB[lane + 32];
            #pragma unroll
            for (int k = 0; k < 32; k++) {
                float m = __shfl_sync(0xffffffffu, ms0, k);
                a0 += m * WT[k * 64 + lane];
                a1 += m * WT[k * 64 + lane + 32];
            }
            #pragma unroll
            for (int k = 0; k < 32; k++) {
                float m = __shfl_sync(0xffffffffu, ms1, k);
                a0 += m * WT[(k + 32) * 64 + lane];
                a1 += m * WT[(k + 32) * 64 + lane + 32];
            }
            #pragma unroll
            for (int k = 0; k < 32; k++) {
                float m = __shfl_sync(0xffffffffu, mt0, k);
                a0 += m * WT[(k + 64) * 64 + lane];
                a1 += m * WT[(k + 64) * 64 + lane + 32];
            }
            #pragma unroll
            for (int k = 0; k < 32; k++) {
                float m = __shfl_sync(0xffffffffu, mt1, k);
                a0 += m * WT[(k + 96) * 64 + lane];
                a1 += m * WT[(k + 96) * 64 + lane + 32];
            }
            o0 = a0; o1 = a1; t0 = a0; t1 = a1;   // users: both paths get user_emb
        } else {
            o0 = ms0; o1 = ms1; t0 = mt0; t1 = mt1;
        }

        g_xt[base + lane]      = t0;
        g_xt[base + 32 + lane] = t1;
        float* er = g_embs + (size_t)v * EMB_COLS + (size_t)(layer + 1) * DIM;
        er[lane]      = o0;
        er[lane + 32] = o1;
    }
}

// ---------------------------------------------------------------------------
// Prediction head: warp per link. dot([ue|ie], pred_w)+b -> leaky_relu -> sigmoid
// ---------------------------------------------------------------------------
__global__ void k_pred(const int* __restrict__ link,
                       const float* __restrict__ pred_w,
                       const float* __restrict__ pred_b,
                       float* __restrict__ out) {
    __shared__ float pw[512];
    for (int i = threadIdx.x; i < 512; i += blockDim.x) pw[i] = pred_w[i];
    __syncthreads();

    int lane = threadIdx.x & 31;
    int warp = threadIdx.x >> 5;
    int j = blockIdx.x * (blockDim.x >> 5) + warp;
    if (j >= N_LINK) return;

    int u  = __ldg(&link[j]);
    int it = __ldg(&link[N_LINK + j]);
    const float* ue = g_embs + (size_t)u  * EMB_COLS;
    const float* ie = g_embs + (size_t)it * EMB_COLS;

    float acc = 0.f;
    #pragma unroll
    for (int c = 0; c < 8; c++) acc += ue[lane + c * 32] * pw[lane + c * 32];
    #pragma unroll
    for (int c = 0; c < 8; c++) acc += ie[lane + c * 32] * pw[256 + lane + c * 32];

    #pragma unroll
    for (int o = 16; o > 0; o >>= 1) acc += __shfl_down_sync(0xffffffffu, acc, o);

    if (lane == 0) {
        float z = acc + pred_b[0];
        z = (z >= 0.f) ? z : 0.01f * z;          // leaky_relu(0.01)
        out[j] = 1.f / (1.f + expf(-z));         // sigmoid
    }
}

// ---------------------------------------------------------------------------
// Launch
// ---------------------------------------------------------------------------
extern "C" void kernel_launch(void* const* d_in, const int* in_sizes, int n_in,
                              void* d_out, int out_size) {
    const int*   sei    = (const int*)  d_in[0];   // [2,E] source graph
    const int*   tei    = (const int*)  d_in[1];   // [2,E] target graph
    const int*   link   = (const int*)  d_in[2];   // [2,NLINK]
    const float* emb    = (const float*)d_in[3];   // [N,64]
    const float* mix_w  = (const float*)d_in[4];   // [3,64,128]
    const float* mix_b  = (const float*)d_in[5];   // [3,64]
    const float* pred_w = (const float*)d_in[6];   // [1,512]
    const float* pred_b = (const float*)d_in[7];   // [1]
    float*       out    = (float*)d_out;           // [NLINK]

    const int* s_src = sei;
    const int* s_dst = sei + E_EDGES;
    const int* t_src = tei;
    const int* t_dst = tei + E_EDGES;

    // ---- CSR build (edge lists are layer-invariant) ----
    k_zero_deg<<<(N_NODES + 255) / 256, 256>>>();
    k_hist<<<(int)((E_EDGES + 255) / 256), 256>>>(s_dst, t_dst);
    k_scan1<<<dim3(NB_SCAN, 2), 1024>>>();
    k_scan2<<<1, 256>>>();
    k_scan3<<<(N_NODES + 255) / 256, 256>>>();
    k_fill<<<(int)((E_EDGES + 255) / 256), 256>>>(s_src, s_dst, t_src, t_dst);

    k_copy_emb<<<(int)(((long)N_NODES * 16 + 255) / 256), 256>>>(
        reinterpret_cast<const float4*>(emb));

    // half-warp per node: N/2 warps per conv
    const int conv_blocks = (int)(((long)(N_NODES / 2) * 32 + 255) / 256);

    for (int l = 0; l < LAYERS; l++) {
        const float* xs = (l == 0) ? emb : (g_embs + (size_t)l * DIM);
        int xs_stride   = (l == 0) ? DIM : EMB_COLS;
        k_conv<<<conv_blocks, 256>>>(xs, xs_stride, g_row_s, g_deg_s,
                                     g_invdeg_s, g_csr_s, g_means);
        const float* xtp = (l == 0) ? emb : g_xt;
        k_conv<<<conv_blocks, 256>>>(xtp, DIM, g_row_t, g_deg_t,
                                     g_invdeg_t, g_csr_t, g_meant);

        k_combine<<<2960, 256>>>(mix_w, mix_b, l);
    }

    k_pred<<<(N_LINK + 7) / 8, 256>>>(link, pred_w, pred_b, out);
}

// round 8
// speedup vs baseline: 7.2582x; 1.0403x over previous
#include <cuda_runtime.h>
#include <cuda_bf16.h>
#include <math.h>

// Problem constants
static constexpr int   N_NODES  = 200000;
static constexpr int   N_USERS  = 100000;
static constexpr int   DIM      = 64;
static constexpr int   LAYERS   = 3;
static constexpr int   E_EDGES  = 3000000;
static constexpr int   N_LINK   = 100000;
static constexpr int   EMB_COLS = (LAYERS + 1) * DIM;            // 256
static constexpr int   CSR_CAP  = E_EDGES + 8 * N_NODES + 64;    // padded capacity

// ---------------------------------------------------------------------------
// Scratch. All row-indexed feature tables have a ZERO GUARD ROW at index 0
// (node v lives at row v+1). Guard rows are never written -> stay zero from
// .bss initialization forever. CSR entries store (src+1); padding entries are
// 0 and therefore gather the guard row (adds 0.0). deg/csr/cursors are zeroed
// by k_tail at the END of each call (and by .bss before the first call), so
// every call sees identical starting state and does identical work.
// ---------------------------------------------------------------------------
__device__ int   g_deg_s[N_NODES],  g_deg_t[N_NODES];
__device__ int   g_row_s[N_NODES],  g_row_t[N_NODES];
__device__ int   g_cur_s[N_NODES],  g_cur_t[N_NODES];
__device__ int   g_tot_s,           g_tot_t;
__device__ int   g_csr_s[CSR_CAP],  g_csr_t[CSR_CAP];
__device__ float g_invdeg_s[N_NODES], g_invdeg_t[N_NODES];
__device__ float g_means[(size_t)(N_NODES + 1) * DIM];       // +guard
__device__ float g_meant[(size_t)(N_NODES + 1) * DIM];       // +guard
__device__ float g_xt   [(size_t)(N_NODES + 1) * DIM];       // +guard
__device__ float g_embs [(size_t)(N_NODES + 1) * EMB_COLS];  // +guard

// ---------------------------------------------------------------------------
// (1) Histogram degrees for both graphs (deg arrays are pre-zeroed).
// ---------------------------------------------------------------------------
__global__ void k_hist(const int* __restrict__ s_dst, const int* __restrict__ t_dst) {
    int e = blockIdx.x * blockDim.x + threadIdx.x;
    if (e < E_EDGES) {
        atomicAdd(&g_deg_s[s_dst[e]], 1);
        atomicAdd(&g_deg_t[t_dst[e]], 1);
    }
}

// ---------------------------------------------------------------------------
// (2) Claim padded CSR segments via atomic cursor (no scan needed -- segment
// order is irrelevant for a gather). Also: invdeg + copy emb into g_embs
// column block 0 (rows shifted by +1 for the guard).
// ---------------------------------------------------------------------------
__global__ void k_offsets(const float4* __restrict__ emb4) {
    int stride = gridDim.x * blockDim.x;
    int t0 = blockIdx.x * blockDim.x + threadIdx.x;

    for (int i = t0; i < N_NODES; i += stride) {
        int ds = g_deg_s[i], dt = g_deg_t[i];
        int ps = (ds + 7) & ~7, pt = (dt + 7) & ~7;
        int rs = atomicAdd(&g_tot_s, ps);
        int rt = atomicAdd(&g_tot_t, pt);
        g_row_s[i] = rs;  g_cur_s[i] = rs;
        g_row_t[i] = rt;  g_cur_t[i] = rt;
        g_invdeg_s[i] = 1.f / fmaxf((float)ds, 1.f);
        g_invdeg_t[i] = 1.f / fmaxf((float)dt, 1.f);
    }
    // copy emb -> g_embs rows 1..N, columns [0,64)
    const long NF4 = (long)N_NODES * (DIM / 4);
    for (long i = t0; i < NF4; i += stride) {
        long v = i >> 4;                // node (0-based)
        int  d = (int)(i & 15);
        reinterpret_cast<float4*>(g_embs)[(v + 1) * (EMB_COLS / 4) + d] = emb4[i];
    }
}

// ---------------------------------------------------------------------------
// (3) Fill CSR: store src+1 (0 is reserved for the zero guard row).
// ---------------------------------------------------------------------------
__global__ void k_fill(const int* __restrict__ s_src, const int* __restrict__ s_dst,
                       const int* __restrict__ t_src, const int* __restrict__ t_dst) {
    int e = blockIdx.x * blockDim.x + threadIdx.x;
    if (e < E_EDGES) {
        int ps = atomicAdd(&g_cur_s[s_dst[e]], 1);
        g_csr_s[ps] = s_src[e] + 1;
        int pt = atomicAdd(&g_cur_t[t_dst[e]], 1);
        g_csr_t[pt] = t_src[e] + 1;
    }
}

// ---------------------------------------------------------------------------
// (4..) Gather conv: HALF-WARP per node, float4 (LDG.128) lanes.
// Rows padded to multiple of 8 -> fixed 8-unrolled, branch-free body.
// 8 independent gathers in flight per iteration (high MLP); padding gathers
// hit the L1-resident guard row. Writes pre-scaled mean (1-based rows).
// ---------------------------------------------------------------------------
__global__ void __launch_bounds__(256)
k_conv(const float* __restrict__ x, int xstr,
       const int* __restrict__ rowptr, const int* __restrict__ degp,
       const float* __restrict__ invd, const int* __restrict__ csr,
       float* __restrict__ om, int nN) {
    int w = (blockIdx.x * blockDim.x + threadIdx.x) >> 5;
    if (w >= nN / 2) return;
    int      lane = threadIdx.x & 31;
    int      h    = lane >> 4;                      // half-warp id
    int      c    = lane & 15;                      // float4 chunk in row
    unsigned hm   = h ? 0xFFFF0000u : 0x0000FFFFu;
    int      v    = 2 * w + h;                      // 0-based node

    int start = rowptr[v];
    int d     = degp[v];
    int p8    = (d + 7) & ~7;

    float4 acc = make_float4(0.f, 0.f, 0.f, 0.f);

    for (int j0 = 0; j0 < p8; j0 += 8) {
        int idx = __ldg(&csr[start + j0 + (c & 7)]);   // 8 entries (dup in halves)
        #pragma unroll
        for (int j = 0; j < 8; j++) {
            int s = __shfl_sync(hm, idx, h * 16 + j);
            float4 vv = __ldg(reinterpret_cast<const float4*>(
                                  x + (size_t)s * xstr) + c);
            acc.x += vv.x; acc.y += vv.y; acc.z += vv.z; acc.w += vv.w;
        }
    }

    float iv = invd[v];
    float4 o = make_float4(acc.x * iv, acc.y * iv, acc.z * iv, acc.w * iv);
    reinterpret_cast<float4*>(om + (size_t)(v + 1) * DIM)[c] = o;
}

// ---------------------------------------------------------------------------
// Combine: users get mix GEMM ue=[ms|mt]@W^T+b; write source slice into
// g_embs(layer+1); write target into g_xt unless last layer. 1-based rows.
// ---------------------------------------------------------------------------
__global__ void __launch_bounds__(256)
k_combine(const float* __restrict__ mix_w, const float* __restrict__ mix_b,
          int layer, int write_xt) {
    __shared__ float WT[128 * 64];   // WT[k*64 + d] = W[d,k]
    __shared__ float BB[64];

    const float* W = mix_w + (size_t)layer * 64 * 128;
    for (int i = threadIdx.x; i < 64 * 128; i += blockDim.x) {
        int k = i >> 6, d = i & 63;
        WT[i] = W[d * 128 + k];
    }
    if (threadIdx.x < 64) BB[threadIdx.x] = mix_b[layer * 64 + threadIdx.x];
    __syncthreads();

    int lane = threadIdx.x & 31;
    int warp = threadIdx.x >> 5;
    int wpb  = blockDim.x >> 5;

    for (int v = blockIdx.x * wpb + warp; v < N_NODES; v += gridDim.x * wpb) {
        size_t base = (size_t)(v + 1) * DIM;

        float ms0 = g_means[base + lane];
        float ms1 = g_means[base + 32 + lane];
        float mt0 = g_meant[base + lane];
        float mt1 = g_meant[base + 32 + lane];

        float o0, o1, t0, t1;
        if (v < N_USERS) {
            float a0 = BB[lane], a1 = BB[lane + 32];
            #pragma unroll
            for (int k = 0; k < 32; k++) {
                float m = __shfl_sync(0xffffffffu, ms0, k);
                a0 += m * WT[k * 64 + lane];
                a1 += m * WT[k * 64 + lane + 32];
            }
            #pragma unroll
            for (int k = 0; k < 32; k++) {
                float m = __shfl_sync(0xffffffffu, ms1, k);
                a0 += m * WT[(k + 32) * 64 + lane];
                a1 += m * WT[(k + 32) * 64 + lane + 32];
            }
            #pragma unroll
            for (int k = 0; k < 32; k++) {
                float m = __shfl_sync(0xffffffffu, mt0, k);
                a0 += m * WT[(k + 64) * 64 + lane];
                a1 += m * WT[(k + 64) * 64 + lane + 32];
            }
            #pragma unroll
            for (int k = 0; k < 32; k++) {
                float m = __shfl_sync(0xffffffffu, mt1, k);
                a0 += m * WT[(k + 96) * 64 + lane];
                a1 += m * WT[(k + 96) * 64 + lane + 32];
            }
            o0 = a0; o1 = a1; t0 = a0; t1 = a1;
        } else {
            o0 = ms0; o1 = ms1; t0 = mt0; t1 = mt1;
        }

        if (write_xt) {
            g_xt[base + lane]      = t0;
            g_xt[base + 32 + lane] = t1;
        }
        float* er = g_embs + (size_t)(v + 1) * EMB_COLS + (size_t)(layer + 1) * DIM;
        er[lane]      = o0;
        er[lane + 32] = o1;
    }
}

// ---------------------------------------------------------------------------
// Prediction head: warp per link (1-based rows).
// ---------------------------------------------------------------------------
__global__ void k_pred(const int* __restrict__ link,
                       const float* __restrict__ pred_w,
                       const float* __restrict__ pred_b,
                       float* __restrict__ out) {
    __shared__ float pw[512];
    for (int i = threadIdx.x; i < 512; i += blockDim.x) pw[i] = pred_w[i];
    __syncthreads();

    int lane = threadIdx.x & 31;
    int warp = threadIdx.x >> 5;
    int j = blockIdx.x * (blockDim.x >> 5) + warp;
    if (j >= N_LINK) return;

    int u  = __ldg(&link[j]) + 1;
    int it = __ldg(&link[N_LINK + j]) + 1;
    const float* ue = g_embs + (size_t)u  * EMB_COLS;
    const float* ie = g_embs + (size_t)it * EMB_COLS;

    float acc = 0.f;
    #pragma unroll
    for (int c = 0; c < 8; c++) acc += ue[lane + c * 32] * pw[lane + c * 32];
    #pragma unroll
    for (int c = 0; c < 8; c++) acc += ie[lane + c * 32] * pw[256 + lane + c * 32];

    #pragma unroll
    for (int o = 16; o > 0; o >>= 1) acc += __shfl_down_sync(0xffffffffu, acc, o);

    if (lane == 0) {
        float z = acc + pred_b[0];
        z = (z >= 0.f) ? z : 0.01f * z;
        out[j] = 1.f / (1.f + expf(-z));
    }
}

// ---------------------------------------------------------------------------
// Tail: restore the zero state (deg, totals, csr) for the next call.
// ---------------------------------------------------------------------------
__global__ void k_tail() {
    int stride = gridDim.x * blockDim.x;
    int t0 = blockIdx.x * blockDim.x + threadIdx.x;
    for (int i = t0; i < CSR_CAP; i += stride) { g_csr_s[i] = 0; g_csr_t[i] = 0; }
    for (int i = t0; i < N_NODES; i += stride) { g_deg_s[i] = 0; g_deg_t[i] = 0; }
    if (t0 == 0) { g_tot_s = 0; g_tot_t = 0; }
}

// ---------------------------------------------------------------------------
// Launch. Sequence (capture slot = our 4th launch => first k_conv profiled):
//   1 k_hist, 2 k_offsets, 3 k_fill, 4 k_conv(S,l0), ...
// ---------------------------------------------------------------------------
extern "C" void kernel_launch(void* const* d_in, const int* in_sizes, int n_in,
                              void* d_out, int out_size) {
    const int*   sei    = (const int*)  d_in[0];
    const int*   tei    = (const int*)  d_in[1];
    const int*   link   = (const int*)  d_in[2];
    const float* emb    = (const float*)d_in[3];
    const float* mix_w  = (const float*)d_in[4];
    const float* mix_b  = (const float*)d_in[5];
    const float* pred_w = (const float*)d_in[6];
    const float* pred_b = (const float*)d_in[7];
    float*       out    = (float*)d_out;

    const int* s_src = sei;
    const int* s_dst = sei + E_EDGES;
    const int* t_src = tei;
    const int* t_dst = tei + E_EDGES;

    k_hist   <<<(E_EDGES + 255) / 256, 256>>>(s_dst, t_dst);
    k_offsets<<<4096, 256>>>(reinterpret_cast<const float4*>(emb));
    k_fill   <<<(E_EDGES + 255) / 256, 256>>>(s_src, s_dst, t_src, t_dst);

    for (int l = 0; l < LAYERS; l++) {
        // source conv (reads g_embs slice l, stride 256)
        k_conv<<<(N_NODES / 2 * 32 + 255) / 256, 256>>>(
            g_embs + (size_t)l * DIM, EMB_COLS,
            g_row_s, g_deg_s, g_invdeg_s, g_csr_s, g_means, N_NODES);
        // target conv: layer0 reads g_embs slice 0; layers>=1 read g_xt.
        // Last layer: only user rows are ever consumed.
        const float* xt  = (l == 0) ? g_embs : g_xt;
        int          xts = (l == 0) ? EMB_COLS : DIM;
        int          nT  = (l == LAYERS - 1) ? N_USERS : N_NODES;
        k_conv<<<(nT / 2 * 32 + 255) / 256, 256>>>(
            xt, xts, g_row_t, g_deg_t, g_invdeg_t, g_csr_t, g_meant, nT);

        k_combine<<<2960, 256>>>(mix_w, mix_b, l, l < LAYERS - 1 ? 1 : 0);
    }

    k_pred<<<(N_LINK + 7) / 8, 256>>>(link, pred_w, pred_b, out);
    k_tail<<<4096, 256>>>();
}